// round 1
// baseline (speedup 1.0000x reference)
#include <cuda_runtime.h>

// Problem constants
#define BB   64      // batch
#define NN   8192    // nodes
#define DIN  64
#define DOUT 64
#define DD   10      // embedding dim
#define CC   4       // clients
#define NPC  2048    // nodes per client

#define K1_CHUNKS 16
#define K1_NODES  (NN / K1_CHUNKS)   // 512 nodes per chunk

#define NT 8   // nodes per block in main kernel
#define BT 8   // batch tile in main kernel

// Scratch (device globals; no runtime allocation allowed)
__device__ float g_part[BB * K1_CHUNKS * DD * DIN];   // 2.6 MB
__device__ float g_sumEH[BB * DD * DIN];              // 160 KB

// ---------------------------------------------------------------------------
// Kernel 1: partial sum_EH[b,chunk,d,i] = sum over chunk nodes of
//           relu(E[g,d]) * (x[b,g,i] * mask[b,g])
// grid: (K1_CHUNKS, BB), block: 256
// ---------------------------------------------------------------------------
__global__ __launch_bounds__(256) void k1_partial(
    const float* __restrict__ x, const float* __restrict__ emb,
    const float* __restrict__ mask, const int* __restrict__ nodes_per)
{
    __shared__ float s_tE[K1_NODES * DD];   // 20 KB
    __shared__ int   s_g[K1_NODES];         // 2 KB
    __shared__ float s_red[8][DD * DIN];    // 20 KB

    const int t = threadIdx.x;
    const int b = blockIdx.y, chunk = blockIdx.x;
    const int p0 = chunk * K1_NODES;

    for (int p = t; p < K1_NODES; p += 256) s_g[p] = nodes_per[p0 + p];
    __syncthreads();
    for (int e = t; e < K1_NODES * DD; e += 256) {
        int p = e / DD, d = e - p * DD;
        s_tE[e] = fmaxf(emb[(size_t)s_g[p] * DD + d], 0.f);
    }
    __syncthreads();

    const int w = t >> 5, lane = t & 31;
    float acc0[DD], acc1[DD];
#pragma unroll
    for (int d = 0; d < DD; d++) { acc0[d] = 0.f; acc1[d] = 0.f; }

    const float* xb = x + (size_t)b * NN * DIN;
    const float* mb = mask + (size_t)b * NN;
    const int nodes_per_warp = K1_NODES / 8;  // 64

    for (int j = 0; j < nodes_per_warp; j++) {
        int p = w * nodes_per_warp + j;
        int g = s_g[p];
        float m = mb[g];
        float2 xv = *(const float2*)(xb + (size_t)g * DIN + lane * 2);
        float x0 = xv.x * m, x1 = xv.y * m;
#pragma unroll
        for (int d = 0; d < DD; d++) {
            float e = s_tE[p * DD + d];
            acc0[d] = fmaf(e, x0, acc0[d]);
            acc1[d] = fmaf(e, x1, acc1[d]);
        }
    }
#pragma unroll
    for (int d = 0; d < DD; d++) {
        *(float2*)&s_red[w][d * DIN + lane * 2] = make_float2(acc0[d], acc1[d]);
    }
    __syncthreads();
    for (int di = t; di < DD * DIN; di += 256) {
        float s = 0.f;
#pragma unroll
        for (int w2 = 0; w2 < 8; w2++) s += s_red[w2][di];
        g_part[((size_t)b * K1_CHUNKS + chunk) * (DD * DIN) + di] = s;
    }
}

// ---------------------------------------------------------------------------
// Kernel 2: reduce chunk partials -> g_sumEH[b,d,i]
// ---------------------------------------------------------------------------
__global__ __launch_bounds__(256) void k2_reduce()
{
    int idx = blockIdx.x * 256 + threadIdx.x;
    if (idx >= BB * DD * DIN) return;
    int b = idx / (DD * DIN), di = idx - b * (DD * DIN);
    float s = 0.f;
#pragma unroll
    for (int k = 0; k < K1_CHUNKS; k++)
        s += g_part[((size_t)b * K1_CHUNKS + k) * (DD * DIN) + di];
    g_sumEH[idx] = s;
}

// ---------------------------------------------------------------------------
// Kernel 3: fused main kernel. One block = 8 nodes (same client), all batches.
//   Phase 0: gather E, relu, bias combine
//   Phase 1: W[nt] = sum_d E[nt,d] * Wp[c,d]  (into smem, 131 KB)
//   Phase 2: per batch-tile of 8: Z = x*mask + tE @ sumEH;  out = Z @ W + bb
// ---------------------------------------------------------------------------
struct Smem3 {
    float sW[NT * DIN * DOUT];     // 131072 B  [nt][k][o]
    float sZ[BT * NT * DIN];       // 16384 B   [bb][nt][k]
    float sSum[BT * DD * DIN];     // 20480 B   [bb][d][i]
    float sE[NT * DD];
    float stE[NT * DD];
    float sbb[NT * DOUT];
    int   sIdx[NT];
};

__global__ __launch_bounds__(256, 1) void k3_main(
    const float* __restrict__ x, const float* __restrict__ emb,
    const float* __restrict__ mask, const float* __restrict__ wpool,
    const float* __restrict__ bpool, const int* __restrict__ nodes_per,
    float* __restrict__ out)
{
    extern __shared__ __align__(16) char smem_raw[];
    Smem3& S = *reinterpret_cast<Smem3*>(smem_raw);

    const int t = threadIdx.x;
    const int node0 = blockIdx.x * NT;
    const int c = node0 / NPC;

    if (t < NT) S.sIdx[t] = nodes_per[node0 + t];
    __syncthreads();
    if (t < NT * DD) {
        int nt = t / DD, d = t - nt * DD;
        float v = emb[(size_t)S.sIdx[nt] * DD + d];
        S.sE[t] = v;
        S.stE[t] = fmaxf(v, 0.f);
    }
    __syncthreads();

    // bias: bb[nt,o] = sum_d E[nt,d] * bpool[c,d,o]
    for (int e = t; e < NT * DOUT; e += 256) {
        int nt = e >> 6, o = e & 63;
        float s = 0.f;
#pragma unroll
        for (int d = 0; d < DD; d++)
            s = fmaf(S.sE[nt * DD + d], bpool[((size_t)c * DD + d) * DOUT + o], s);
        S.sbb[e] = s;
    }

    // W generation: 4096 (i,o) pairs, each thread owns 16, processed 4 at a time
    const float* wpc = wpool + (size_t)c * DD * DIN * DOUT;
#pragma unroll
    for (int pg = 0; pg < 16; pg += 4) {
        float acc[4][NT];
#pragma unroll
        for (int q = 0; q < 4; q++)
#pragma unroll
            for (int nt = 0; nt < NT; nt++) acc[q][nt] = 0.f;
#pragma unroll
        for (int d = 0; d < DD; d++) {
            float wp[4];
#pragma unroll
            for (int q = 0; q < 4; q++)
                wp[q] = wpc[(size_t)d * (DIN * DOUT) + (pg + q) * 256 + t];
            float ev[NT];
#pragma unroll
            for (int nt = 0; nt < NT; nt++) ev[nt] = S.sE[nt * DD + d];
#pragma unroll
            for (int q = 0; q < 4; q++)
#pragma unroll
                for (int nt = 0; nt < NT; nt++)
                    acc[q][nt] = fmaf(wp[q], ev[nt], acc[q][nt]);
        }
#pragma unroll
        for (int q = 0; q < 4; q++) {
            int pair = (pg + q) * 256 + t;
#pragma unroll
            for (int nt = 0; nt < NT; nt++)
                S.sW[nt * (DIN * DOUT) + pair] = acc[q][nt];
        }
    }
    __syncthreads();

    const int nt = t >> 5;
    const int lane = t & 31;
    const int i2 = lane * 2;
    const int g = S.sIdx[nt];

    for (int bt = 0; bt < BB / BT; bt++) {
        const int b0 = bt * BT;
        // load sumEH tile for these batches
        for (int e = t; e < BT * DD * DIN; e += 256) {
            int bb = e / (DD * DIN), di = e - bb * (DD * DIN);
            S.sSum[e] = g_sumEH[(size_t)(b0 + bb) * (DD * DIN) + di];
        }
        __syncthreads();

        // Z generation: Z[bb][nt][i] = x[b,g,i]*mask + sum_d tE[nt,d]*sumEH[b,d,i]
#pragma unroll
        for (int bb = 0; bb < BT; bb++) {
            int b = b0 + bb;
            float m = mask[(size_t)b * NN + g];
            float2 xv = *(const float2*)(x + ((size_t)b * NN + g) * DIN + i2);
            float z0 = xv.x * m, z1 = xv.y * m;
#pragma unroll
            for (int d = 0; d < DD; d++) {
                float e = S.stE[nt * DD + d];
                float2 sv = *(const float2*)&S.sSum[(bb * DD + d) * DIN + i2];
                z0 = fmaf(e, sv.x, z0);
                z1 = fmaf(e, sv.y, z1);
            }
            *(float2*)&S.sZ[(bb * NT + nt) * DIN + i2] = make_float2(z0, z1);
        }
        __syncthreads();

        // GEMM: out[b, node, o] = Z[b,node,:] @ W[node] + bb
        const int o2 = i2;
        float acc0[BT], acc1[BT];
        float bias0 = S.sbb[nt * DOUT + o2];
        float bias1 = S.sbb[nt * DOUT + o2 + 1];
#pragma unroll
        for (int bb = 0; bb < BT; bb++) { acc0[bb] = bias0; acc1[bb] = bias1; }

#pragma unroll 4
        for (int k4 = 0; k4 < DIN; k4 += 4) {
            float4 zv[BT];
#pragma unroll
            for (int bb = 0; bb < BT; bb++)
                zv[bb] = *(const float4*)&S.sZ[(bb * NT + nt) * DIN + k4];
#pragma unroll
            for (int kk = 0; kk < 4; kk++) {
                float2 wv = *(const float2*)&S.sW[(nt * DIN + k4 + kk) * DOUT + o2];
#pragma unroll
                for (int bb = 0; bb < BT; bb++) {
                    float zz = (&zv[bb].x)[kk];
                    acc0[bb] = fmaf(zz, wv.x, acc0[bb]);
                    acc1[bb] = fmaf(zz, wv.y, acc1[bb]);
                }
            }
        }

#pragma unroll
        for (int bb = 0; bb < BT; bb++) {
            *(float2*)(out + ((size_t)(b0 + bb) * NN + node0 + nt) * DOUT + o2) =
                make_float2(acc0[bb], acc1[bb]);
        }
        __syncthreads();
    }
}

// ---------------------------------------------------------------------------
extern "C" void kernel_launch(void* const* d_in, const int* in_sizes, int n_in,
                              void* d_out, int out_size)
{
    const float* x     = (const float*)d_in[0];
    const float* emb   = (const float*)d_in[1];
    // d_in[2] = poly_coefficients (unused in sprtrelu mode)
    const float* mask  = (const float*)d_in[3];
    const float* wpool = (const float*)d_in[4];
    const float* bpool = (const float*)d_in[5];
    const int*   nodes = (const int*)d_in[6];
    float* out = (float*)d_out;

    cudaFuncSetAttribute(k3_main, cudaFuncAttributeMaxDynamicSharedMemorySize,
                         (int)sizeof(Smem3));

    dim3 g1(K1_CHUNKS, BB);
    k1_partial<<<g1, 256>>>(x, emb, mask, nodes);

    int tot = BB * DD * DIN;
    k2_reduce<<<(tot + 255) / 256, 256>>>();

    k3_main<<<NN / NT, 256, sizeof(Smem3)>>>(x, emb, mask, wpool, bpool, nodes, out);
}

// round 2
// speedup vs baseline: 1.0602x; 1.0602x over previous
#include <cuda_runtime.h>

// Problem constants
#define BB   64      // batch
#define NN   8192    // nodes
#define DIN  64
#define DOUT 64
#define DD   10      // embedding dim
#define CC   4       // clients
#define NPC  2048    // nodes per client

#define K1_CHUNKS 16
#define K1_NODES  (NN / K1_CHUNKS)   // 512 nodes per chunk

#define NT 8   // nodes per block in main kernel
#define BT 8   // batch tile in main kernel

typedef unsigned long long u64;

// packed f32x2 helpers (FFMA2 path — ptxas never emits it from C++)
__device__ __forceinline__ u64 pk2(float lo, float hi) {
    u64 r; asm("mov.b64 %0,{%1,%2};" : "=l"(r) : "f"(lo), "f"(hi)); return r;
}
__device__ __forceinline__ u64 dup2(float v) { return pk2(v, v); }
__device__ __forceinline__ void f2fma(u64& d, u64 a, u64 b) {
    asm("fma.rn.f32x2 %0,%1,%2,%3;" : "=l"(d) : "l"(a), "l"(b), "l"(d));
}
__device__ __forceinline__ float2 u2f(u64 v) {
    float2 f; asm("mov.b64 {%0,%1},%2;" : "=f"(f.x), "=f"(f.y) : "l"(v)); return f;
}

// Scratch (device globals; no runtime allocation allowed)
__device__ float g_part[BB * K1_CHUNKS * DD * DIN];   // 2.6 MB
__device__ float g_sumEH[BB * DD * DIN];              // 160 KB

// ---------------------------------------------------------------------------
// Kernel 1: partial sum_EH[b,chunk,d,i] = sum over chunk nodes of
//           relu(E[g,d]) * (x[b,g,i] * mask[b,g])
// grid: (K1_CHUNKS, BB), block: 256.  Unroll-4 + batched prefetch for MLP.
// ---------------------------------------------------------------------------
__global__ __launch_bounds__(256) void k1_partial(
    const float* __restrict__ x, const float* __restrict__ emb,
    const float* __restrict__ mask, const int* __restrict__ nodes_per)
{
    __shared__ float s_tE[K1_NODES * DD];   // 20 KB
    __shared__ int   s_g[K1_NODES];         // 2 KB
    __shared__ float s_red[8][DD * DIN];    // 20 KB

    const int t = threadIdx.x;
    const int b = blockIdx.y, chunk = blockIdx.x;
    const int p0 = chunk * K1_NODES;

    for (int p = t; p < K1_NODES; p += 256) s_g[p] = nodes_per[p0 + p];
    __syncthreads();
    for (int e = t; e < K1_NODES * DD; e += 256) {
        int p = e / DD, d = e - p * DD;
        s_tE[e] = fmaxf(emb[(size_t)s_g[p] * DD + d], 0.f);
    }
    __syncthreads();

    const int w = t >> 5, lane = t & 31;
    float acc0[DD], acc1[DD];
#pragma unroll
    for (int d = 0; d < DD; d++) { acc0[d] = 0.f; acc1[d] = 0.f; }

    const float* xb = x + (size_t)b * NN * DIN;
    const float* mb = mask + (size_t)b * NN;
    const int base = w * (K1_NODES / 8);   // 64 nodes per warp

#pragma unroll 1
    for (int j = 0; j < K1_NODES / 8; j += 4) {
        int g4[4]; float m4[4]; float2 x4[4];
#pragma unroll
        for (int q = 0; q < 4; q++) g4[q] = s_g[base + j + q];
#pragma unroll
        for (int q = 0; q < 4; q++) {
            m4[q] = __ldg(&mb[g4[q]]);
            x4[q] = *(const float2*)(xb + (size_t)g4[q] * DIN + lane * 2);
        }
#pragma unroll
        for (int q = 0; q < 4; q++) {
            float x0 = x4[q].x * m4[q], x1 = x4[q].y * m4[q];
            const float* te = &s_tE[(base + j + q) * DD];
#pragma unroll
            for (int d = 0; d < DD; d++) {
                acc0[d] = fmaf(te[d], x0, acc0[d]);
                acc1[d] = fmaf(te[d], x1, acc1[d]);
            }
        }
    }
#pragma unroll
    for (int d = 0; d < DD; d++)
        *(float2*)&s_red[w][d * DIN + lane * 2] = make_float2(acc0[d], acc1[d]);
    __syncthreads();
    for (int di = t; di < DD * DIN; di += 256) {
        float s = 0.f;
#pragma unroll
        for (int w2 = 0; w2 < 8; w2++) s += s_red[w2][di];
        g_part[((size_t)b * K1_CHUNKS + chunk) * (DD * DIN) + di] = s;
    }
}

// ---------------------------------------------------------------------------
// Kernel 2: reduce chunk partials -> g_sumEH[b,d,i]
// ---------------------------------------------------------------------------
__global__ __launch_bounds__(256) void k2_reduce()
{
    int idx = blockIdx.x * 256 + threadIdx.x;
    if (idx >= BB * DD * DIN) return;
    int b = idx / (DD * DIN), di = idx - b * (DD * DIN);
    float s = 0.f;
#pragma unroll
    for (int k = 0; k < K1_CHUNKS; k++)
        s += g_part[((size_t)b * K1_CHUNKS + k) * (DD * DIN) + di];
    g_sumEH[idx] = s;
}

// ---------------------------------------------------------------------------
// Kernel 3: fused main kernel, packed f32x2 math throughout.
// One block = 8 nodes (same client).
// ---------------------------------------------------------------------------
struct Smem3 {
    float sW[NT * DIN * DOUT];     // 131072 B  [nt][k][o]
    float sZ[BT * NT * DIN];       // 16384 B   [bb][nt][k]
    float sSum[BT * DD * DIN];     // 20480 B   [bb][d][i]
    float sE[NT * DD];
    float sbb[NT * DOUT];
    int   sIdx[NT];
};

__global__ __launch_bounds__(256, 1) void k3_main(
    const float* __restrict__ x, const float* __restrict__ emb,
    const float* __restrict__ mask, const float* __restrict__ wpool,
    const float* __restrict__ bpool, const int* __restrict__ nodes_per,
    float* __restrict__ out)
{
    extern __shared__ __align__(16) char smem_raw[];
    Smem3& S = *reinterpret_cast<Smem3*>(smem_raw);

    const int t = threadIdx.x;
    const int node0 = blockIdx.x * NT;
    const int c = node0 / NPC;

    if (t < NT) S.sIdx[t] = nodes_per[node0 + t];
    __syncthreads();
    if (t < NT * DD) {
        int nt = t / DD, d = t - nt * DD;
        S.sE[t] = emb[(size_t)S.sIdx[nt] * DD + d];
    }
    __syncthreads();

    // bias: bb[nt,o] = sum_d E[nt,d] * bpool[c,d,o]   (tiny, scalar)
    for (int e = t; e < NT * DOUT; e += 256) {
        int nt = e >> 6, o = e & 63;
        float s = 0.f;
#pragma unroll
        for (int d = 0; d < DD; d++)
            s = fmaf(S.sE[nt * DD + d], bpool[((size_t)c * DD + d) * DOUT + o], s);
        S.sbb[e] = s;
    }

    // W generation (packed): thread owns 4 consecutive (i,o)-pairs per pg.
    // pair = pg*1024 + t*4 ; W[nt][pair..pair+3] += E[nt,d] * Wp[c,d,pair..]
    const float* wpc = wpool + (size_t)c * DD * DIN * DOUT;
#pragma unroll
    for (int pg = 0; pg < 4; pg++) {
        u64 acc[2][NT];
#pragma unroll
        for (int h = 0; h < 2; h++)
#pragma unroll
            for (int nt = 0; nt < NT; nt++) acc[h][nt] = 0ull;
#pragma unroll
        for (int d = 0; d < DD; d++) {
            ulonglong2 wp = *(const ulonglong2*)&wpc[(size_t)d * (DIN * DOUT) + pg * 1024 + t * 4];
#pragma unroll
            for (int nt = 0; nt < NT; nt++) {
                u64 ed = dup2(S.sE[nt * DD + d]);
                f2fma(acc[0][nt], wp.x, ed);
                f2fma(acc[1][nt], wp.y, ed);
            }
        }
#pragma unroll
        for (int nt = 0; nt < NT; nt++) {
            *(float2*)&S.sW[nt * (DIN * DOUT) + pg * 1024 + t * 4]     = u2f(acc[0][nt]);
            *(float2*)&S.sW[nt * (DIN * DOUT) + pg * 1024 + t * 4 + 2] = u2f(acc[1][nt]);
        }
    }
    __syncthreads();

    const int nt = t >> 5;
    const int lane = t & 31;
    const int g = S.sIdx[nt];

    // hoisted packed relu(E[nt,:]) for Z-gen
    u64 edup[DD];
#pragma unroll
    for (int d = 0; d < DD; d++) edup[d] = dup2(fmaxf(S.sE[nt * DD + d], 0.f));

    // GEMM lane mapping: 16 lanes cover o (4 each), 2 halves cover bb (4 each)
    const int o0 = (lane & 15) * 4;
    const int bb0 = (lane >> 4) * 4;
    const int i2 = lane * 2;

    for (int bt = 0; bt < BB / BT; bt++) {
        const int b0 = bt * BT;
        // load sumEH tile for these batches
        for (int e = t; e < BT * DD * DIN; e += 256) {
            int bb = e / (DD * DIN), di = e - bb * (DD * DIN);
            S.sSum[e] = g_sumEH[(size_t)(b0 + bb) * (DD * DIN) + di];
        }
        __syncthreads();

        // Z-gen (packed over i-pair): Z[bb][nt][i2,i2+1]
#pragma unroll
        for (int bb = 0; bb < BT; bb++) {
            int b = b0 + bb;
            float m = mask[(size_t)b * NN + g];
            float2 xv = *(const float2*)(x + ((size_t)b * NN + g) * DIN + i2);
            u64 z = pk2(xv.x * m, xv.y * m);
#pragma unroll
            for (int d = 0; d < DD; d++) {
                u64 sv = *(const u64*)&S.sSum[(bb * DD + d) * DIN + i2];
                f2fma(z, edup[d], sv);
            }
            *(float2*)&S.sZ[(bb * NT + nt) * DIN + i2] = u2f(z);
        }
        __syncthreads();

        // GEMM: out[b, node, o0..o0+3] for bb0..bb0+3, packed over o-pairs
        u64 acc[4][2];
        {
            ulonglong2 bv = *(const ulonglong2*)&S.sbb[nt * DOUT + o0];
#pragma unroll
            for (int j = 0; j < 4; j++) { acc[j][0] = bv.x; acc[j][1] = bv.y; }
        }
#pragma unroll 8
        for (int k = 0; k < DIN; k += 2) {
            ulonglong2 w0 = *(const ulonglong2*)&S.sW[(nt * DIN + k) * DOUT + o0];
            ulonglong2 w1 = *(const ulonglong2*)&S.sW[(nt * DIN + k + 1) * DOUT + o0];
#pragma unroll
            for (int j = 0; j < 4; j++) {
                float2 zz = *(const float2*)&S.sZ[((bb0 + j) * NT + nt) * DIN + k];
                u64 z0 = dup2(zz.x), z1 = dup2(zz.y);
                f2fma(acc[j][0], z0, w0.x);
                f2fma(acc[j][1], z0, w0.y);
                f2fma(acc[j][0], z1, w1.x);
                f2fma(acc[j][1], z1, w1.y);
            }
        }
#pragma unroll
        for (int j = 0; j < 4; j++) {
            float2 p0 = u2f(acc[j][0]), p1 = u2f(acc[j][1]);
            float4 o4 = make_float4(p0.x, p0.y, p1.x, p1.y);
            *(float4*)(out + ((size_t)(b0 + bb0 + j) * NN + node0 + nt) * DOUT + o0) = o4;
        }
        __syncthreads();
    }
}

// ---------------------------------------------------------------------------
extern "C" void kernel_launch(void* const* d_in, const int* in_sizes, int n_in,
                              void* d_out, int out_size)
{
    const float* x     = (const float*)d_in[0];
    const float* emb   = (const float*)d_in[1];
    // d_in[2] = poly_coefficients (unused in sprtrelu mode)
    const float* mask  = (const float*)d_in[3];
    const float* wpool = (const float*)d_in[4];
    const float* bpool = (const float*)d_in[5];
    const int*   nodes = (const int*)d_in[6];
    float* out = (float*)d_out;

    cudaFuncSetAttribute(k3_main, cudaFuncAttributeMaxDynamicSharedMemorySize,
                         (int)sizeof(Smem3));

    dim3 g1(K1_CHUNKS, BB);
    k1_partial<<<g1, 256>>>(x, emb, mask, nodes);

    int tot = BB * DD * DIN;
    k2_reduce<<<(tot + 255) / 256, 256>>>();

    k3_main<<<NN / NT, 256, sizeof(Smem3)>>>(x, emb, mask, wpool, bpool, nodes, out);
}